// round 12
// baseline (speedup 1.0000x reference)
#include <cuda_runtime.h>
#include <math.h>

#define B_  2
#define C_  384
#define HW  1024
#define NHEAD 12
#define NGROUP 6
#define HC  32
#define GC  64
#define NS  1024
#define SCALE 0.17677669529663687f   // 1/sqrt(32)

// ---------------- scratch ----------------------------------------------------
__device__ float g_q  [B_ * C_ * HW];
__device__ float g_pos[B_ * NGROUP * NS * 2];
__device__ float g_xs [B_ * NGROUP * GC * NS];
__device__ float g_k  [B_ * C_ * NS];
__device__ float g_v  [B_ * C_ * NS];
__device__ float g_o  [B_ * C_ * HW];

// ---------------- helpers ----------------------------------------------------
__device__ __forceinline__ unsigned f2tf32(float f) {
    unsigned r;
    asm("cvt.rna.tf32.f32 %0, %1;" : "=r"(r) : "f"(f));
    return r;
}

__device__ __forceinline__ void mma_tf32(float d[4], const unsigned a[4], unsigned b0, unsigned b1) {
    asm volatile(
        "mma.sync.aligned.m16n8k8.row.col.f32.tf32.tf32.f32 "
        "{%0,%1,%2,%3}, {%4,%5,%6,%7}, {%8,%9}, {%0,%1,%2,%3};"
        : "+f"(d[0]), "+f"(d[1]), "+f"(d[2]), "+f"(d[3])
        : "r"(a[0]), "r"(a[1]), "r"(a[2]), "r"(a[3]), "r"(b0), "r"(b1));
}

__device__ __forceinline__ void cp_async16(void* smem_dst, const void* gmem_src) {
    unsigned s = (unsigned)__cvta_generic_to_shared(smem_dst);
    asm volatile("cp.async.cg.shared.global [%0], [%1], 16;" :: "r"(s), "l"(gmem_src));
}
#define CP_COMMIT() asm volatile("cp.async.commit_group;")
#define CP_WAIT(n)  asm volatile("cp.async.wait_group %0;" :: "n"(n))

// ---------------- tf32 tensor-core projection GEMM (3-stage cp.async) --------
#define BM 64
#define BN 128
#define BK 16
#define APAD 20     // 80B row stride (16B multiple)
#define BPAD 136    // 544B row stride (16B multiple)
#define GSTG 3

__device__ __forceinline__ void mma_gemm_core(
        float* __restrict__ Yb, const float* __restrict__ W,
        const float* __restrict__ bias, const float* __restrict__ Xb,
        int o0, int p0) {
    __shared__ __align__(16) float Asf[GSTG][BM][APAD];
    __shared__ __align__(16) float Bsf[GSTG][BK][BPAD];

    int tid = threadIdx.x;
    int lane = tid & 31, warp = tid >> 5;
    int wm = warp & 1, wn = warp >> 1;
    int qr = lane >> 2, qc = lane & 3;

    float d[2][8][4];
    #pragma unroll
    for (int mt = 0; mt < 2; mt++)
        #pragma unroll
        for (int nt = 0; nt < 8; nt++)
            #pragma unroll
            for (int r = 0; r < 4; r++) d[mt][nt][r] = 0.f;

    #define ISSUE_TILE(s, k0)                                                             \
        _Pragma("unroll")                                                                 \
        for (int j = 0; j < 2; j++) {                                                     \
            int id = tid * 2 + j; int row = id >> 2, c16 = id & 3;                        \
            cp_async16(&Asf[s][row][c16 * 4],                                             \
                       &W[(size_t)(o0 + row) * C_ + (k0) + c16 * 4]);                     \
        }                                                                                 \
        _Pragma("unroll")                                                                 \
        for (int j = 0; j < 4; j++) {                                                     \
            int id = tid + j * 128; int row = id >> 5, c16 = id & 31;                     \
            cp_async16(&Bsf[s][row][c16 * 4],                                             \
                       &Xb[(size_t)((k0) + row) * HW + p0 + c16 * 4]);                    \
        }

    ISSUE_TILE(0, 0);      CP_COMMIT();
    ISSUE_TILE(1, BK);     CP_COMMIT();

    const int NIT = C_ / BK;   // 24
    for (int it = 0; it < NIT; it++) {
        if (it < NIT - 1) { CP_WAIT(1); } else { CP_WAIT(0); }
        __syncthreads();
        int s = it % GSTG;
        #pragma unroll
        for (int ks = 0; ks < 2; ks++) {
            int kb = ks * 8;
            unsigned af[2][4];
            #pragma unroll
            for (int mt = 0; mt < 2; mt++) {
                int rbse = wm * 32 + mt * 16;
                af[mt][0] = f2tf32(Asf[s][rbse + qr    ][kb + qc    ]);
                af[mt][1] = f2tf32(Asf[s][rbse + qr + 8][kb + qc    ]);
                af[mt][2] = f2tf32(Asf[s][rbse + qr    ][kb + qc + 4]);
                af[mt][3] = f2tf32(Asf[s][rbse + qr + 8][kb + qc + 4]);
            }
            #pragma unroll
            for (int nt = 0; nt < 8; nt++) {
                int nb = wn * 64 + nt * 8 + qr;
                unsigned b0 = f2tf32(Bsf[s][kb + qc    ][nb]);
                unsigned b1 = f2tf32(Bsf[s][kb + qc + 4][nb]);
                mma_tf32(d[0][nt], af[0], b0, b1);
                mma_tf32(d[1][nt], af[1], b0, b1);
            }
        }
        if (it + 2 < NIT) { ISSUE_TILE((it + 2) % GSTG, (it + 2) * BK); }
        CP_COMMIT();
    }
    #undef ISSUE_TILE

    #pragma unroll
    for (int mt = 0; mt < 2; mt++) {
        int ob = o0 + wm * 32 + mt * 16 + qr;
        float bv0 = bias[ob], bv1 = bias[ob + 8];
        #pragma unroll
        for (int nt = 0; nt < 8; nt++) {
            int p = p0 + wn * 64 + nt * 8 + 2 * qc;
            *(float2*)&Yb[(size_t)ob * HW + p] =
                make_float2(d[mt][nt][0] + bv0, d[mt][nt][1] + bv0);
            *(float2*)&Yb[(size_t)(ob + 8) * HW + p] =
                make_float2(d[mt][nt][2] + bv1, d[mt][nt][3] + bv1);
        }
    }
}

__global__ __launch_bounds__(128) void mma_gemm_kernel(
        float* __restrict__ Y, const float* __restrict__ W,
        const float* __restrict__ X, const float* __restrict__ bias) {
    int b = blockIdx.z;
    mma_gemm_core(Y + (size_t)b * C_ * HW, W, bias, X + (size_t)b * C_ * HW,
                  blockIdx.y * BM, blockIdx.x * BN);
}

__global__ __launch_bounds__(128) void mma_gemm_kv_kernel(
        float* __restrict__ K, const float* __restrict__ Wk, const float* __restrict__ bk,
        float* __restrict__ V, const float* __restrict__ Wv, const float* __restrict__ bv,
        const float* __restrict__ X) {
    int b = blockIdx.z;
    int yy = blockIdx.y;
    const float* W  = (yy < 6) ? Wk : Wv;
    const float* bb = (yy < 6) ? bk : bv;
    float* Y        = (yy < 6) ? K  : V;
    mma_gemm_core(Y + (size_t)b * C_ * NS, W, bb, X + (size_t)b * C_ * NS,
                  (yy % 6) * BM, blockIdx.x * BN);
}

// ---------------- offset branch (row-based, sliding window) -------------------
__global__ __launch_bounds__(256) void offset2_kernel(
        const float* __restrict__ q,
        const float* __restrict__ dw_w, const float* __restrict__ dw_b,
        const float* __restrict__ ln_g, const float* __restrict__ ln_b,
        const float* __restrict__ pw_w, float* __restrict__ pos) {
    int y  = blockIdx.x;
    int bg = blockIdx.y;
    int b = bg / NGROUP, g = bg % NGROUP;
    int t = threadIdx.x;
    int c = t & 63, xq = t >> 6;

    const float* qc = q + ((size_t)b * C_ + g * GC + c) * HW;
    const float* w  = dw_w + c * 49;

    float out[8];
    float bb = dw_b[c];
    #pragma unroll
    for (int i = 0; i < 8; i++) out[i] = bb;

    #pragma unroll
    for (int dy = 0; dy < 7; dy++) {
        int yy = y + dy - 3;
        if (yy < 0 || yy > 31) continue;
        const float* row = qc + yy * 32;
        float rb[14];
        #pragma unroll
        for (int j = 0; j < 14; j++) {
            int xx = xq * 8 - 3 + j;
            rb[j] = ((unsigned)xx < 32u) ? row[xx] : 0.f;
        }
        #pragma unroll
        for (int dx = 0; dx < 7; dx++) {
            float wv = w[dy * 7 + dx];
            #pragma unroll
            for (int i = 0; i < 8; i++) out[i] += wv * rb[i + dx];
        }
    }

    __shared__ float co[64][33];
    #pragma unroll
    for (int i = 0; i < 8; i++) co[c][xq * 8 + i] = out[i];
    __syncthreads();

    int x  = t >> 3;
    int cp = t & 7;
    __shared__ float red[32][8];
    __shared__ float mus[32], ivs[32], oys[32];

    float ps = 0.f;
    #pragma unroll
    for (int j = 0; j < 8; j++) ps += co[cp * 8 + j][x];
    red[x][cp] = ps;
    __syncthreads();
    if (t < 32) {
        float s = 0.f;
        #pragma unroll
        for (int j = 0; j < 8; j++) s += red[t][j];
        mus[t] = s * (1.f / 64.f);
    }
    __syncthreads();
    float mu = mus[x];
    float pv = 0.f;
    #pragma unroll
    for (int j = 0; j < 8; j++) { float dd = co[cp * 8 + j][x] - mu; pv += dd * dd; }
    red[x][cp] = pv;
    __syncthreads();
    if (t < 32) {
        float s = 0.f;
        #pragma unroll
        for (int j = 0; j < 8; j++) s += red[t][j];
        ivs[t] = rsqrtf(s * (1.f / 64.f) + 1e-5f);
    }
    __syncthreads();
    float iv = ivs[x];
    float p0 = 0.f, p1 = 0.f;
    #pragma unroll
    for (int j = 0; j < 8; j++) {
        int ch = cp * 8 + j;
        float on = (co[ch][x] - mu) * iv * ln_g[ch] + ln_b[ch];
        float ge = 0.5f * on * (1.f + erff(on * 0.70710678118654752f));
        p0 += ge * pw_w[ch];
        p1 += ge * pw_w[GC + ch];
    }
    red[x][cp] = p0;
    __syncthreads();
    if (t < 32) {
        float s = 0.f;
        #pragma unroll
        for (int j = 0; j < 8; j++) s += red[t][j];
        oys[t] = s;
    }
    __syncthreads();
    red[x][cp] = p1;
    __syncthreads();
    if (t < 32) {
        float s = 0.f;
        #pragma unroll
        for (int j = 0; j < 8; j++) s += red[t][j];
        float off_y = tanhf(oys[t]) * (2.0f / 32.0f);
        float off_x = tanhf(s)      * (2.0f / 32.0f);
        float ry = ((float)y + 0.5f) * (1.f / 16.f) - 1.f;
        float rx = ((float)t + 0.5f) * (1.f / 16.f) - 1.f;
        int s_idx = y * 32 + t;
        pos[(bg * NS + s_idx) * 2 + 0] = off_y + ry;
        pos[(bg * NS + s_idx) * 2 + 1] = off_x + rx;
    }
}

// ---------------- grid sample -> xs ------------------------------------------
__global__ void sample_kernel(const float* __restrict__ x, const float* __restrict__ pos,
                              float* __restrict__ xs) {
    int idx = blockIdx.x * blockDim.x + threadIdx.x;
    if (idx >= B_ * NGROUP * GC * NS) return;
    int s  = idx & 1023;
    int c  = (idx >> 10) & 63;
    int bg = idx >> 16;
    int b = bg / NGROUP, g = bg % NGROUP;
    float py = pos[(bg * NS + s) * 2 + 0];
    float px = pos[(bg * NS + s) * 2 + 1];
    float gx = (px + 1.f) * 0.5f * 31.f;
    float gy = (py + 1.f) * 0.5f * 31.f;
    float x0f = floorf(gx), y0f = floorf(gy);
    float wx = gx - x0f, wy = gy - y0f;
    int x0 = (int)x0f, y0 = (int)y0f;
    const float* img = x + ((size_t)b * C_ + g * GC + c) * HW;
    float acc = 0.f;
    bool x0v = (unsigned)x0 < 32u, x1v = (unsigned)(x0 + 1) < 32u;
    bool y0v = (unsigned)y0 < 32u, y1v = (unsigned)(y0 + 1) < 32u;
    if (x0v && y0v) acc += (1.f - wx) * (1.f - wy) * img[y0 * 32 + x0];
    if (x1v && y0v) acc += wx * (1.f - wy)         * img[y0 * 32 + x0 + 1];
    if (x0v && y1v) acc += (1.f - wx) * wy         * img[(y0 + 1) * 32 + x0];
    if (x1v && y1v) acc += wx * wy                 * img[(y0 + 1) * 32 + x0 + 1];
    xs[idx] = acc;
}

// ---------------- tensor-core flash attention (cp.async pipelined) -----------
// ALL segment offsets are multiples of 4 words (16B) — required by cp.async16.
#define TAB_W   3969
#define QS_OFF  3972                      // align up from 3969
#define KF_OFF  (QS_OFF + 64 * 36)        // 6276 words (25104 B, 16B-aligned)
#define VF_OFF  (KF_OFF + 3 * 32 * 68)    // +6528 -> 12804
#define PS_OFF  (VF_OFF + 3 * 32 * 68)    // 19332
#define PB_OFF  (PS_OFF + 64 * 68)        // 23684 (16B-aligned)
#define ATTN_SMEM_WORDS (PB_OFF + 3 * 128)
#define KV_STG_W (32 * 68)                // 2176 words, 16B multiple

__device__ __forceinline__ float bilin_s(const float* __restrict__ tab, float gy, float gx) {
    float x0f = floorf(gx), y0f = floorf(gy);
    float wx = gx - x0f, wy = gy - y0f;
    int x0 = (int)x0f, y0 = (int)y0f;
    bool x0v = (unsigned)x0 < 63u, x1v = (unsigned)(x0 + 1) < 63u;
    bool y0v = (unsigned)y0 < 63u, y1v = (unsigned)(y0 + 1) < 63u;
    float r = 0.f;
    if (x0v && y0v) r += (1.f - wx) * (1.f - wy) * tab[y0 * 63 + x0];
    if (x1v && y0v) r += wx * (1.f - wy)         * tab[y0 * 63 + x0 + 1];
    if (x0v && y1v) r += (1.f - wx) * wy         * tab[(y0 + 1) * 63 + x0];
    if (x1v && y1v) r += wx * wy                 * tab[(y0 + 1) * 63 + x0 + 1];
    return r;
}

__global__ __launch_bounds__(128) void attn3_kernel(
        const float* __restrict__ q, const float* __restrict__ k,
        const float* __restrict__ v, const float* __restrict__ pos,
        const float* __restrict__ rpe, float* __restrict__ out) {
    extern __shared__ __align__(16) unsigned smem_u[];
    float*    tab  = (float*)smem_u;
    unsigned* Qs   = smem_u + QS_OFF;
    float*    Kf   = (float*)(smem_u + KF_OFF);
    float*    Vf   = (float*)(smem_u + VF_OFF);
    unsigned* Ps   = smem_u + PS_OFF;
    float*    posb = (float*)(smem_u + PB_OFF);

    int bh = blockIdx.y;
    int b = bh / NHEAD, h = bh % NHEAD;
    int bg = b * NGROUP + (h >> 1);
    int m0 = blockIdx.x * 64;
    int tid = threadIdx.x;
    int lane = tid & 31, warp = tid >> 5;
    int qr = lane >> 2, qc = lane & 3;

    const float* qb = q + ((size_t)b * C_ + h * HC) * HW;
    const float* kb = k + ((size_t)b * C_ + h * HC) * NS;
    const float* vb = v + ((size_t)b * C_ + h * HC) * NS;
    const float* tg = rpe + h * 63 * 63;
    const float* pg = pos + (size_t)bg * NS * 2;

    #define ATTN_ISSUE(s, n0)                                                             \
        _Pragma("unroll")                                                                 \
        for (int j = 0; j < 4; j++) {                                                     \
            int id = tid + j * 128; int row = id >> 4, c16 = id & 15;                     \
            cp_async16(&Kf[(s) * KV_STG_W + row * 68 + c16 * 4],                          \
                       &kb[(size_t)row * NS + (n0) + c16 * 4]);                           \
            cp_async16(&Vf[(s) * KV_STG_W + row * 68 + c16 * 4],                          \
                       &vb[(size_t)row * NS + (n0) + c16 * 4]);                           \
        }                                                                                 \
        if (tid < 32) cp_async16(&posb[(s) * 128 + tid * 4], &pg[(n0) * 2 + tid * 4]);

    ATTN_ISSUE(0, 0);  CP_COMMIT();
    ATTN_ISSUE(1, 64); CP_COMMIT();

    for (int i = tid; i < TAB_W; i += 128) tab[i] = tg[i];
    for (int i = tid; i < 64 * 32; i += 128) {
        int c = i >> 6, m = i & 63;
        Qs[m * 36 + c] = f2tf32(qb[(size_t)c * HW + m0 + m]);
    }

    int r0 = warp * 16 + qr;
    int mA = m0 + r0, mB = mA + 8;
    float qyA = ((float)(mA >> 5) + 0.5f) * (1.f / 16.f) - 1.f;
    float qxA = ((float)(mA & 31) + 0.5f) * (1.f / 16.f) - 1.f;
    float qyB = ((float)(mB >> 5) + 0.5f) * (1.f / 16.f) - 1.f;
    float qxB = ((float)(mB & 31) + 0.5f) * (1.f / 16.f) - 1.f;

    float mrA = -1e30f, mrB = -1e30f, lrA = 0.f, lrB = 0.f;
    float O[4][4] = {};
    unsigned af[4][4];
    bool af_done = false;

    for (int i = 0; i < 16; i++) {
        if (i < 15) { CP_WAIT(1); } else { CP_WAIT(0); }
        __syncthreads();
        if (!af_done) {
            #pragma unroll
            for (int kc = 0; kc < 4; kc++) {
                af[kc][0] = Qs[(r0    ) * 36 + kc * 8 + qc    ];
                af[kc][1] = Qs[(r0 + 8) * 36 + kc * 8 + qc    ];
                af[kc][2] = Qs[(r0    ) * 36 + kc * 8 + qc + 4];
                af[kc][3] = Qs[(r0 + 8) * 36 + kc * 8 + qc + 4];
            }
            af_done = true;
        }
        const float* Ks = Kf + (i % 3) * KV_STG_W;
        const float* Vs = Vf + (i % 3) * KV_STG_W;
        const float* pb = posb + (i % 3) * 128;

        float s[8][4];
        #pragma unroll
        for (int ct = 0; ct < 8; ct++) { s[ct][0] = s[ct][1] = s[ct][2] = s[ct][3] = 0.f; }
        #pragma unroll
        for (int ct = 0; ct < 8; ct++) {
            #pragma unroll
            for (int kc = 0; kc < 4; kc++) {
                unsigned b0 = f2tf32(Ks[(kc * 8 + qc    ) * 68 + ct * 8 + qr]);
                unsigned b1 = f2tf32(Ks[(kc * 8 + qc + 4) * 68 + ct * 8 + qr]);
                mma_tf32(s[ct], af[kc], b0, b1);
            }
        }

        #pragma unroll
        for (int ct = 0; ct < 8; ct++) {
            #pragma unroll
            for (int j = 0; j < 2; j++) {
                int nl = ct * 8 + 2 * qc + j;
                float py = pb[2 * nl], px = pb[2 * nl + 1];
                float gyA = ((qyA - py) * 0.5f + 1.f) * 31.f;
                float gxA = ((qxA - px) * 0.5f + 1.f) * 31.f;
                float gyB = ((qyB - py) * 0.5f + 1.f) * 31.f;
                float gxB = ((qxB - px) * 0.5f + 1.f) * 31.f;
                s[ct][j]     = s[ct][j]     * SCALE + bilin_s(tab, gyA, gxA);
                s[ct][2 + j] = s[ct][2 + j] * SCALE + bilin_s(tab, gyB, gxB);
            }
        }

        float tmA = -1e30f, tmB = -1e30f;
        #pragma unroll
        for (int ct = 0; ct < 8; ct++) {
            tmA = fmaxf(tmA, fmaxf(s[ct][0], s[ct][1]));
            tmB = fmaxf(tmB, fmaxf(s[ct][2], s[ct][3]));
        }
        tmA = fmaxf(tmA, __shfl_xor_sync(0xffffffffu, tmA, 1));
        tmA = fmaxf(tmA, __shfl_xor_sync(0xffffffffu, tmA, 2));
        tmB = fmaxf(tmB, __shfl_xor_sync(0xffffffffu, tmB, 1));
        tmB = fmaxf(tmB, __shfl_xor_sync(0xffffffffu, tmB, 2));
        float mnA = fmaxf(mrA, tmA), mnB = fmaxf(mrB, tmB);
        float aA = __expf(mrA - mnA), aB = __expf(mrB - mnB);
        mrA = mnA; mrB = mnB;

        float rsA = 0.f, rsB = 0.f;
        #pragma unroll
        for (int ct = 0; ct < 8; ct++) {
            s[ct][0] = __expf(s[ct][0] - mnA);
            s[ct][1] = __expf(s[ct][1] - mnA);
            s[ct][2] = __expf(s[ct][2] - mnB);
            s[ct][3] = __expf(s[ct][3] - mnB);
            rsA += s[ct][0] + s[ct][1];
            rsB += s[ct][2] + s[ct][3];
            Ps[(r0    ) * 68 + ct * 8 + 2 * qc    ] = f2tf32(s[ct][0]);
            Ps[(r0    ) * 68 + ct * 8 + 2 * qc + 1] = f2tf32(s[ct][1]);
            Ps[(r0 + 8) * 68 + ct * 8 + 2 * qc    ] = f2tf32(s[ct][2]);
            Ps[(r0 + 8) * 68 + ct * 8 + 2 * qc + 1] = f2tf32(s[ct][3]);
        }
        rsA += __shfl_xor_sync(0xffffffffu, rsA, 1);
        rsA += __shfl_xor_sync(0xffffffffu, rsA, 2);
        rsB += __shfl_xor_sync(0xffffffffu, rsB, 1);
        rsB += __shfl_xor_sync(0xffffffffu, rsB, 2);
        lrA = lrA * aA + rsA;
        lrB = lrB * aB + rsB;
        #pragma unroll
        for (int ct = 0; ct < 4; ct++) {
            O[ct][0] *= aA; O[ct][1] *= aA;
            O[ct][2] *= aB; O[ct][3] *= aB;
        }
        __syncwarp();

        #pragma unroll
        for (int kc = 0; kc < 8; kc++) {
            unsigned pa[4];
            pa[0] = Ps[(r0    ) * 68 + kc * 8 + qc    ];
            pa[1] = Ps[(r0 + 8) * 68 + kc * 8 + qc    ];
            pa[2] = Ps[(r0    ) * 68 + kc * 8 + qc + 4];
            pa[3] = Ps[(r0 + 8) * 68 + kc * 8 + qc + 4];
            #pragma unroll
            for (int ct = 0; ct < 4; ct++) {
                unsigned b0 = f2tf32(Vs[(ct * 8 + qr) * 68 + kc * 8 + qc    ]);
                unsigned b1 = f2tf32(Vs[(ct * 8 + qr) * 68 + kc * 8 + qc + 4]);
                mma_tf32(O[ct], pa, b0, b1);
            }
        }
        __syncwarp();

        if (i + 2 < 16) { ATTN_ISSUE((i + 2) % 3, (i + 2) * 64); }
        CP_COMMIT();
    }
    #undef ATTN_ISSUE

    float invA = 1.f / lrA, invB = 1.f / lrB;
    float* ob = out + ((size_t)b * C_ + h * HC) * HW;
    #pragma unroll
    for (int ct = 0; ct < 4; ct++) {
        int c0 = ct * 8 + 2 * qc, c1 = c0 + 1;
        ob[(size_t)c0 * HW + m0 + r0    ] = O[ct][0] * invA;
        ob[(size_t)c1 * HW + m0 + r0    ] = O[ct][1] * invA;
        ob[(size_t)c0 * HW + m0 + r0 + 8] = O[ct][2] * invB;
        ob[(size_t)c1 * HW + m0 + r0 + 8] = O[ct][3] * invB;
    }
}

// ---------------- launch -----------------------------------------------------
extern "C" void kernel_launch(void* const* d_in, const int* in_sizes, int n_in,
                              void* d_out, int out_size) {
    const float* x      = (const float*)d_in[0];
    const float* Wq     = (const float*)d_in[1];
    const float* bq     = (const float*)d_in[2];
    const float* Wk     = (const float*)d_in[3];
    const float* bk     = (const float*)d_in[4];
    const float* Wv     = (const float*)d_in[5];
    const float* bv     = (const float*)d_in[6];
    const float* Wo     = (const float*)d_in[7];
    const float* bo     = (const float*)d_in[8];
    const float* dw_w   = (const float*)d_in[9];
    const float* dw_b   = (const float*)d_in[10];
    const float* ln_g   = (const float*)d_in[11];
    const float* ln_b   = (const float*)d_in[12];
    const float* pw_w   = (const float*)d_in[13];
    const float* rpe    = (const float*)d_in[14];
    float* y = (float*)d_out;

    float *q, *pos, *xs, *k, *v, *o;
    cudaGetSymbolAddress((void**)&q,   g_q);
    cudaGetSymbolAddress((void**)&pos, g_pos);
    cudaGetSymbolAddress((void**)&xs,  g_xs);
    cudaGetSymbolAddress((void**)&k,   g_k);
    cudaGetSymbolAddress((void**)&v,   g_v);
    cudaGetSymbolAddress((void**)&o,   g_o);

    static int smem_set = 0;
    if (!smem_set) {
        cudaFuncSetAttribute(attn3_kernel, cudaFuncAttributeMaxDynamicSharedMemorySize,
                             ATTN_SMEM_WORDS * 4);
        smem_set = 1;
    }

    dim3 ggrid(HW / BN, C_ / BM, B_);

    mma_gemm_kernel<<<ggrid, 128>>>(q, Wq, x, bq);

    dim3 ogrid(32, B_ * NGROUP);
    offset2_kernel<<<ogrid, 256>>>(q, dw_w, dw_b, ln_g, ln_b, pw_w, pos);

    sample_kernel<<<(B_ * NGROUP * GC * NS + 255) / 256, 256>>>(x, pos, xs);

    dim3 kvgrid(HW / BN, 12, B_);
    mma_gemm_kv_kernel<<<kvgrid, 128>>>(k, Wk, bk, v, Wv, bv, xs);

    dim3 agrid(HW / 64, B_ * NHEAD);
    attn3_kernel<<<agrid, 128, ATTN_SMEM_WORDS * 4>>>(q, k, v, pos, rpe, o);

    mma_gemm_kernel<<<ggrid, 128>>>(y, Wo, o, bo);
}

// round 14
// speedup vs baseline: 1.8831x; 1.8831x over previous
#include <cuda_runtime.h>
#include <math.h>

#define B_  2
#define C_  384
#define HW  1024
#define NHEAD 12
#define NGROUP 6
#define HC  32
#define GC  64
#define NS  1024
#define SCALE 0.17677669529663687f   // 1/sqrt(32)

// ---------------- scratch ----------------------------------------------------
__device__ float g_q  [B_ * C_ * HW];
__device__ float g_pos[B_ * NGROUP * NS * 2];
__device__ float g_xs [B_ * NGROUP * GC * NS];
__device__ float g_k  [B_ * C_ * NS];
__device__ float g_v  [B_ * C_ * NS];
__device__ float g_o  [B_ * C_ * HW];

// ---------------- helpers ----------------------------------------------------
__device__ __forceinline__ unsigned f2tf32(float f) {
    unsigned r;
    asm("cvt.rna.tf32.f32 %0, %1;" : "=r"(r) : "f"(f));
    return r;
}

__device__ __forceinline__ void mma_tf32(float d[4], const unsigned a[4], unsigned b0, unsigned b1) {
    asm volatile(
        "mma.sync.aligned.m16n8k8.row.col.f32.tf32.tf32.f32 "
        "{%0,%1,%2,%3}, {%4,%5,%6,%7}, {%8,%9}, {%0,%1,%2,%3};"
        : "+f"(d[0]), "+f"(d[1]), "+f"(d[2]), "+f"(d[3])
        : "r"(a[0]), "r"(a[1]), "r"(a[2]), "r"(a[3]), "r"(b0), "r"(b1));
}

__device__ __forceinline__ void cp_async16(void* smem_dst, const void* gmem_src) {
    unsigned s = (unsigned)__cvta_generic_to_shared(smem_dst);
    asm volatile("cp.async.cg.shared.global [%0], [%1], 16;" :: "r"(s), "l"(gmem_src));
}
#define CP_COMMIT() asm volatile("cp.async.commit_group;")
#define CP_WAIT(n)  asm volatile("cp.async.wait_group %0;" :: "n"(n))

// ---------------- tf32 tensor-core projection GEMM (3-stage, race-free) ------
#define BM 64
#define BN 128
#define BK 16
#define APAD 20
#define BPAD 136
#define GSTG 3

__device__ __forceinline__ void mma_gemm_core(
        float* __restrict__ Yb, const float* __restrict__ W,
        const float* __restrict__ bias, const float* __restrict__ Xb,
        int o0, int p0) {
    __shared__ __align__(16) float Asf[GSTG][BM][APAD];
    __shared__ __align__(16) float Bsf[GSTG][BK][BPAD];

    int tid = threadIdx.x;
    int lane = tid & 31, warp = tid >> 5;
    int wm = warp & 1, wn = warp >> 1;
    int qr = lane >> 2, qc = lane & 3;

    float d[2][8][4];
    #pragma unroll
    for (int mt = 0; mt < 2; mt++)
        #pragma unroll
        for (int nt = 0; nt < 8; nt++)
            #pragma unroll
            for (int r = 0; r < 4; r++) d[mt][nt][r] = 0.f;

    #define ISSUE_TILE(s, k0)                                                             \
        _Pragma("unroll")                                                                 \
        for (int j = 0; j < 2; j++) {                                                     \
            int id = tid * 2 + j; int row = id >> 2, c16 = id & 3;                        \
            cp_async16(&Asf[s][row][c16 * 4],                                             \
                       &W[(size_t)(o0 + row) * C_ + (k0) + c16 * 4]);                     \
        }                                                                                 \
        _Pragma("unroll")                                                                 \
        for (int j = 0; j < 4; j++) {                                                     \
            int id = tid + j * 128; int row = id >> 5, c16 = id & 31;                     \
            cp_async16(&Bsf[s][row][c16 * 4],                                             \
                       &Xb[(size_t)((k0) + row) * HW + p0 + c16 * 4]);                    \
        }

    ISSUE_TILE(0, 0);      CP_COMMIT();
    ISSUE_TILE(1, BK);     CP_COMMIT();

    const int NIT = C_ / BK;
    for (int it = 0; it < NIT; it++) {
        if (it < NIT - 1) { CP_WAIT(1); } else { CP_WAIT(0); }
        __syncthreads();
        int s = it % GSTG;
        #pragma unroll
        for (int ks = 0; ks < 2; ks++) {
            int kb = ks * 8;
            unsigned af[2][4];
            #pragma unroll
            for (int mt = 0; mt < 2; mt++) {
                int rbse = wm * 32 + mt * 16;
                af[mt][0] = f2tf32(Asf[s][rbse + qr    ][kb + qc    ]);
                af[mt][1] = f2tf32(Asf[s][rbse + qr + 8][kb + qc    ]);
                af[mt][2] = f2tf32(Asf[s][rbse + qr    ][kb + qc + 4]);
                af[mt][3] = f2tf32(Asf[s][rbse + qr + 8][kb + qc + 4]);
            }
            #pragma unroll
            for (int nt = 0; nt < 8; nt++) {
                int nb = wn * 64 + nt * 8 + qr;
                unsigned b0 = f2tf32(Bsf[s][kb + qc    ][nb]);
                unsigned b1 = f2tf32(Bsf[s][kb + qc + 4][nb]);
                mma_tf32(d[0][nt], af[0], b0, b1);
                mma_tf32(d[1][nt], af[1], b0, b1);
            }
        }
        if (it + 2 < NIT) { ISSUE_TILE((it + 2) % GSTG, (it + 2) * BK); }
        CP_COMMIT();
    }
    #undef ISSUE_TILE

    #pragma unroll
    for (int mt = 0; mt < 2; mt++) {
        int ob = o0 + wm * 32 + mt * 16 + qr;
        float bv0 = bias[ob], bv1 = bias[ob + 8];
        #pragma unroll
        for (int nt = 0; nt < 8; nt++) {
            int p = p0 + wn * 64 + nt * 8 + 2 * qc;
            *(float2*)&Yb[(size_t)ob * HW + p] =
                make_float2(d[mt][nt][0] + bv0, d[mt][nt][1] + bv0);
            *(float2*)&Yb[(size_t)(ob + 8) * HW + p] =
                make_float2(d[mt][nt][2] + bv1, d[mt][nt][3] + bv1);
        }
    }
}

__global__ __launch_bounds__(128) void mma_gemm_kernel(
        float* __restrict__ Y, const float* __restrict__ W,
        const float* __restrict__ X, const float* __restrict__ bias) {
    int b = blockIdx.z;
    mma_gemm_core(Y + (size_t)b * C_ * HW, W, bias, X + (size_t)b * C_ * HW,
                  blockIdx.y * BM, blockIdx.x * BN);
}

__global__ __launch_bounds__(128) void mma_gemm_kv_kernel(
        float* __restrict__ K, const float* __restrict__ Wk, const float* __restrict__ bk,
        float* __restrict__ V, const float* __restrict__ Wv, const float* __restrict__ bv,
        const float* __restrict__ X) {
    int b = blockIdx.z;
    int yy = blockIdx.y;
    const float* W  = (yy < 6) ? Wk : Wv;
    const float* bb = (yy < 6) ? bk : bv;
    float* Y        = (yy < 6) ? K  : V;
    mma_gemm_core(Y + (size_t)b * C_ * NS, W, bb, X + (size_t)b * C_ * NS,
                  (yy % 6) * BM, blockIdx.x * BN);
}

// ---------------- offset branch (unchanged) ----------------------------------
__global__ __launch_bounds__(256) void offset2_kernel(
        const float* __restrict__ q,
        const float* __restrict__ dw_w, const float* __restrict__ dw_b,
        const float* __restrict__ ln_g, const float* __restrict__ ln_b,
        const float* __restrict__ pw_w, float* __restrict__ pos) {
    int y  = blockIdx.x;
    int bg = blockIdx.y;
    int b = bg / NGROUP, g = bg % NGROUP;
    int t = threadIdx.x;
    int c = t & 63, xq = t >> 6;

    const float* qc = q + ((size_t)b * C_ + g * GC + c) * HW;
    const float* w  = dw_w + c * 49;

    float out[8];
    float bb = dw_b[c];
    #pragma unroll
    for (int i = 0; i < 8; i++) out[i] = bb;

    #pragma unroll
    for (int dy = 0; dy < 7; dy++) {
        int yy = y + dy - 3;
        if (yy < 0 || yy > 31) continue;
        const float* row = qc + yy * 32;
        float rb[14];
        #pragma unroll
        for (int j = 0; j < 14; j++) {
            int xx = xq * 8 - 3 + j;
            rb[j] = ((unsigned)xx < 32u) ? row[xx] : 0.f;
        }
        #pragma unroll
        for (int dx = 0; dx < 7; dx++) {
            float wv = w[dy * 7 + dx];
            #pragma unroll
            for (int i = 0; i < 8; i++) out[i] += wv * rb[i + dx];
        }
    }

    __shared__ float co[64][33];
    #pragma unroll
    for (int i = 0; i < 8; i++) co[c][xq * 8 + i] = out[i];
    __syncthreads();

    int x  = t >> 3;
    int cp = t & 7;
    __shared__ float red[32][8];
    __shared__ float mus[32], ivs[32], oys[32];

    float ps = 0.f;
    #pragma unroll
    for (int j = 0; j < 8; j++) ps += co[cp * 8 + j][x];
    red[x][cp] = ps;
    __syncthreads();
    if (t < 32) {
        float s = 0.f;
        #pragma unroll
        for (int j = 0; j < 8; j++) s += red[t][j];
        mus[t] = s * (1.f / 64.f);
    }
    __syncthreads();
    float mu = mus[x];
    float pv = 0.f;
    #pragma unroll
    for (int j = 0; j < 8; j++) { float dd = co[cp * 8 + j][x] - mu; pv += dd * dd; }
    red[x][cp] = pv;
    __syncthreads();
    if (t < 32) {
        float s = 0.f;
        #pragma unroll
        for (int j = 0; j < 8; j++) s += red[t][j];
        ivs[t] = rsqrtf(s * (1.f / 64.f) + 1e-5f);
    }
    __syncthreads();
    float iv = ivs[x];
    float p0 = 0.f, p1 = 0.f;
    #pragma unroll
    for (int j = 0; j < 8; j++) {
        int ch = cp * 8 + j;
        float on = (co[ch][x] - mu) * iv * ln_g[ch] + ln_b[ch];
        float ge = 0.5f * on * (1.f + erff(on * 0.70710678118654752f));
        p0 += ge * pw_w[ch];
        p1 += ge * pw_w[GC + ch];
    }
    red[x][cp] = p0;
    __syncthreads();
    if (t < 32) {
        float s = 0.f;
        #pragma unroll
        for (int j = 0; j < 8; j++) s += red[t][j];
        oys[t] = s;
    }
    __syncthreads();
    red[x][cp] = p1;
    __syncthreads();
    if (t < 32) {
        float s = 0.f;
        #pragma unroll
        for (int j = 0; j < 8; j++) s += red[t][j];
        float off_y = tanhf(oys[t]) * (2.0f / 32.0f);
        float off_x = tanhf(s)      * (2.0f / 32.0f);
        float ry = ((float)y + 0.5f) * (1.f / 16.f) - 1.f;
        float rx = ((float)t + 0.5f) * (1.f / 16.f) - 1.f;
        int s_idx = y * 32 + t;
        pos[(bg * NS + s_idx) * 2 + 0] = off_y + ry;
        pos[(bg * NS + s_idx) * 2 + 1] = off_x + rx;
    }
}

// ---------------- grid sample -> xs (unchanged) ------------------------------
__global__ void sample_kernel(const float* __restrict__ x, const float* __restrict__ pos,
                              float* __restrict__ xs) {
    int idx = blockIdx.x * blockDim.x + threadIdx.x;
    if (idx >= B_ * NGROUP * GC * NS) return;
    int s  = idx & 1023;
    int c  = (idx >> 10) & 63;
    int bg = idx >> 16;
    int b = bg / NGROUP, g = bg % NGROUP;
    float py = pos[(bg * NS + s) * 2 + 0];
    float px = pos[(bg * NS + s) * 2 + 1];
    float gx = (px + 1.f) * 0.5f * 31.f;
    float gy = (py + 1.f) * 0.5f * 31.f;
    float x0f = floorf(gx), y0f = floorf(gy);
    float wx = gx - x0f, wy = gy - y0f;
    int x0 = (int)x0f, y0 = (int)y0f;
    const float* img = x + ((size_t)b * C_ + g * GC + c) * HW;
    float acc = 0.f;
    bool x0v = (unsigned)x0 < 32u, x1v = (unsigned)(x0 + 1) < 32u;
    bool y0v = (unsigned)y0 < 32u, y1v = (unsigned)(y0 + 1) < 32u;
    if (x0v && y0v) acc += (1.f - wx) * (1.f - wy) * img[y0 * 32 + x0];
    if (x1v && y0v) acc += wx * (1.f - wy)         * img[y0 * 32 + x0 + 1];
    if (x0v && y1v) acc += (1.f - wx) * wy         * img[(y0 + 1) * 32 + x0];
    if (x1v && y1v) acc += wx * wy                 * img[(y0 + 1) * 32 + x0 + 1];
    xs[idx] = acc;
}

// ---------------- flash attention v4b: 8 warps, n-split, race-fixed ----------
#define TAB_W   3969
#define PS_OFF  3972
#define KF_OFF  (PS_OFF + 4352)
#define VF_OFF  (KF_OFF + 2 * 2176)
#define PB_OFF  (VF_OFF + 2 * 2176)
#define RM_OFF  (PB_OFF + 256)
#define RS_OFF  (RM_OFF + 128)
#define ATTN_SMEM_WORDS (RS_OFF + 128)   // 17540 words = 68.5 KB
#define KV_STG_W (32 * 68)

__device__ __forceinline__ float bilin_c(const float* __restrict__ tab, float gy, float gx) {
    float yf = fminf(fmaxf(floorf(gy), 0.f), 61.f);
    float xf = fminf(fmaxf(floorf(gx), 0.f), 61.f);
    float wy = gy - yf, wx = gx - xf;
    const float* p = tab + (int)yf * 63 + (int)xf;
    float a = p[0], bq = p[1], c = p[63], d = p[64];
    float top = a + wx * (bq - a);
    float bot = c + wx * (d - c);
    return top + wy * (bot - top);
}

__global__ __launch_bounds__(256) void attn4_kernel(
        const float* __restrict__ q, const float* __restrict__ k,
        const float* __restrict__ v, const float* __restrict__ pos,
        const float* __restrict__ rpe, float* __restrict__ out) {
    extern __shared__ __align__(16) unsigned smem_u[];
    float*    tab  = (float*)smem_u;
    unsigned* Qs   = smem_u + PS_OFF;
    unsigned* Ps   = smem_u + PS_OFF;
    float*    Kf   = (float*)(smem_u + KF_OFF);
    float*    Vf   = (float*)(smem_u + VF_OFF);
    float*    posb = (float*)(smem_u + PB_OFF);
    float*    redM = (float*)(smem_u + RM_OFF);
    float*    redS = (float*)(smem_u + RS_OFF);
    float*    Obuf = (float*)(smem_u + KF_OFF);

    int bh = blockIdx.y;
    int b = bh / NHEAD, h = bh % NHEAD;
    int bg = b * NGROUP + (h >> 1);
    int m0 = blockIdx.x * 64;
    int tid = threadIdx.x;
    int lane = tid & 31, warp = tid >> 5;
    int qr = lane >> 2, qc = lane & 3;
    int wr = warp & 3, wn = warp >> 2;
    int r0 = wr * 16 + qr;
    int nh = wn * 32;

    const float* qb = q + ((size_t)b * C_ + h * HC) * HW;
    const float* kb = k + ((size_t)b * C_ + h * HC) * NS;
    const float* vb = v + ((size_t)b * C_ + h * HC) * NS;
    const float* tg = rpe + h * 63 * 63;
    const float* pg = pos + (size_t)bg * NS * 2;

    #define ATTN_ISSUE(s, n0)                                                             \
        _Pragma("unroll")                                                                 \
        for (int j = 0; j < 2; j++) {                                                     \
            int id = tid + j * 256; int row = id >> 4, c16 = id & 15;                     \
            cp_async16(&Kf[(s) * KV_STG_W + row * 68 + c16 * 4],                          \
                       &kb[(size_t)row * NS + (n0) + c16 * 4]);                           \
            cp_async16(&Vf[(s) * KV_STG_W + row * 68 + c16 * 4],                          \
                       &vb[(size_t)row * NS + (n0) + c16 * 4]);                           \
        }                                                                                 \
        if (tid < 32) cp_async16(&posb[(s) * 128 + tid * 4], &pg[(n0) * 2 + tid * 4]);

    ATTN_ISSUE(0, 0);  CP_COMMIT();
    ATTN_ISSUE(1, 64); CP_COMMIT();

    for (int i = tid; i < TAB_W; i += 256) tab[i] = tg[i];
    for (int i = tid; i < 64 * 32; i += 256) {
        int c = i >> 6, m = i & 63;
        Qs[m * 36 + c] = f2tf32(qb[(size_t)c * HW + m0 + m]);
    }
    __syncthreads();

    unsigned af[4][4];
    #pragma unroll
    for (int kc = 0; kc < 4; kc++) {
        af[kc][0] = Qs[(r0    ) * 36 + kc * 8 + qc    ];
        af[kc][1] = Qs[(r0 + 8) * 36 + kc * 8 + qc    ];
        af[kc][2] = Qs[(r0    ) * 36 + kc * 8 + qc + 4];
        af[kc][3] = Qs[(r0 + 8) * 36 + kc * 8 + qc + 4];
    }

    int mA = m0 + r0, mB = mA + 8;
    float qyA = ((float)(mA >> 5) + 0.5f) * (1.f / 16.f) - 1.f;
    float qxA = ((float)(mA & 31) + 0.5f) * (1.f / 16.f) - 1.f;
    float qyB = ((float)(mB >> 5) + 0.5f) * (1.f / 16.f) - 1.f;
    float qxB = ((float)(mB & 31) + 0.5f) * (1.f / 16.f) - 1.f;

    float mrA = -1e30f, mrB = -1e30f, lrA = 0.f, lrB = 0.f;
    float O[4][4] = {};

    for (int i = 0; i < 16; i++) {
        if (i < 15) { CP_WAIT(1); } else { CP_WAIT(0); }
        __syncthreads();
        const float* Ks = Kf + (i & 1) * KV_STG_W;
        const float* Vs = Vf + (i & 1) * KV_STG_W;
        const float* pb = posb + (i & 1) * 128;

        float s[4][4];
        #pragma unroll
        for (int ct = 0; ct < 4; ct++) { s[ct][0] = s[ct][1] = s[ct][2] = s[ct][3] = 0.f; }
        #pragma unroll
        for (int ct = 0; ct < 4; ct++) {
            #pragma unroll
            for (int kc = 0; kc < 4; kc++) {
                unsigned b0 = f2tf32(Ks[(kc * 8 + qc    ) * 68 + nh + ct * 8 + qr]);
                unsigned b1 = f2tf32(Ks[(kc * 8 + qc + 4) * 68 + nh + ct * 8 + qr]);
                mma_tf32(s[ct], af[kc], b0, b1);
            }
        }

        #pragma unroll
        for (int ct = 0; ct < 4; ct++) {
            #pragma unroll
            for (int j = 0; j < 2; j++) {
                int nl = nh + ct * 8 + 2 * qc + j;
                float py = pb[2 * nl], px = pb[2 * nl + 1];
                float gyA = ((qyA - py) * 0.5f + 1.f) * 31.f;
                float gxA = ((qxA - px) * 0.5f + 1.f) * 31.f;
                float gyB = ((qyB - py) * 0.5f + 1.f) * 31.f;
                float gxB = ((qxB - px) * 0.5f + 1.f) * 31.f;
                s[ct][j]     = s[ct][j]     * SCALE + bilin_c(tab, gyA, gxA);
                s[ct][2 + j] = s[ct][2 + j] * SCALE + bilin_c(tab, gyB, gxB);
            }
        }

        float tmA = -1e30f, tmB = -1e30f;
        #pragma unroll
        for (int ct = 0; ct < 4; ct++) {
            tmA = fmaxf(tmA, fmaxf(s[ct][0], s[ct][1]));
            tmB = fmaxf(tmB, fmaxf(s[ct][2], s[ct][3]));
        }
        tmA = fmaxf(tmA, __shfl_xor_sync(0xffffffffu, tmA, 1));
        tmA = fmaxf(tmA, __shfl_xor_sync(0xffffffffu, tmA, 2));
        tmB = fmaxf(tmB, __shfl_xor_sync(0xffffffffu, tmB, 1));
        tmB = fmaxf(tmB, __shfl_xor_sync(0xffffffffu, tmB, 2));
        redM[wn * 64 + r0]     = tmA;
        redM[wn * 64 + r0 + 8] = tmB;
        __syncthreads();
        float toA = redM[(wn ^ 1) * 64 + r0];
        float toB = redM[(wn ^ 1) * 64 + r0 + 8];
        float mnA = fmaxf(mrA, fmaxf(tmA, toA));
        float mnB = fmaxf(mrB, fmaxf(tmB, toB));
        float aA = __expf(mrA - mnA), aB = __expf(mrB - mnB);
        mrA = mnA; mrB = mnB;

        float rsA = 0.f, rsB = 0.f;
        #pragma unroll
        for (int ct = 0; ct < 4; ct++) {
            s[ct][0] = __expf(s[ct][0] - mnA);
            s[ct][1] = __expf(s[ct][1] - mnA);
            s[ct][2] = __expf(s[ct][2] - mnB);
            s[ct][3] = __expf(s[ct][3] - mnB);
            rsA += s[ct][0] + s[ct][1];
            rsB += s[ct][2] + s[ct][3];
            int cb = nh + ct * 8 + 2 * qc;
            Ps[(r0    ) * 68 + cb    ] = f2tf32(s[ct][0]);
            Ps[(r0    ) * 68 + cb + 1] = f2tf32(s[ct][1]);
            Ps[(r0 + 8) * 68 + cb    ] = f2tf32(s[ct][2]);
            Ps[(r0 + 8) * 68 + cb + 1] = f2tf32(s[ct][3]);
        }
        rsA += __shfl_xor_sync(0xffffffffu, rsA, 1);
        rsA += __shfl_xor_sync(0xffffffffu, rsA, 2);
        rsB += __shfl_xor_sync(0xffffffffu, rsB, 1);
        rsB += __shfl_xor_sync(0xffffffffu, rsB, 2);
        redS[wn * 64 + r0]     = rsA;
        redS[wn * 64 + r0 + 8] = rsB;
        __syncthreads();
        rsA += redS[(wn ^ 1) * 64 + r0];
        rsB += redS[(wn ^ 1) * 64 + r0 + 8];
        lrA = lrA * aA + rsA;
        lrB = lrB * aB + rsB;
        #pragma unroll
        for (int ct = 0; ct < 4; ct++) {
            O[ct][0] *= aA; O[ct][1] *= aA;
            O[ct][2] *= aB; O[ct][3] *= aB;
        }

        #pragma unroll
        for (int kc = 0; kc < 4; kc++) {
            int cb = nh + kc * 8;
            unsigned pa[4];
            pa[0] = Ps[(r0    ) * 68 + cb + qc    ];
            pa[1] = Ps[(r0 + 8) * 68 + cb + qc    ];
            pa[2] = Ps[(r0    ) * 68 + cb + qc + 4];
            pa[3] = Ps[(r0 + 8) * 68 + cb + qc + 4];
            #pragma unroll
            for (int ct = 0; ct < 4; ct++) {
                unsigned b0 = f2tf32(Vs[(ct * 8 + qr) * 68 + cb + qc    ]);
                unsigned b1 = f2tf32(Vs[(ct * 8 + qr) * 68 + cb + qc + 4]);
                mma_tf32(O[ct], pa, b0, b1);
            }
        }

        // RACE FIX: drain all warps' reads of stage (i&1) before cp.async
        // overwrites it for iteration i+2 (2-stage ring reuses the stage
        // that was just read this iteration).
        if (i + 2 < 16) { __syncthreads(); ATTN_ISSUE(i & 1, (i + 2) * 64); }
        CP_COMMIT();
    }
    #undef ATTN_ISSUE

    if (wn == 1) {
        #pragma unroll
        for (int ct = 0; ct < 4; ct++) {
            int c0 = ct * 8 + 2 * qc;
            Obuf[(r0    ) * 32 + c0    ] = O[ct][0];
            Obuf[(r0    ) * 32 + c0 + 1] = O[ct][1];
            Obuf[(r0 + 8) * 32 + c0    ] = O[ct][2];
            Obuf[(r0 + 8) * 32 + c0 + 1] = O[ct][3];
        }
    }
    __syncthreads();
    if (wn == 0) {
        float invA = 1.f / lrA, invB = 1.f / lrB;
        float* ob = out + ((size_t)b * C_ + h * HC) * HW;
        #pragma unroll
        for (int ct = 0; ct < 4; ct++) {
            int c0 = ct * 8 + 2 * qc, c1 = c0 + 1;
            ob[(size_t)c0 * HW + m0 + r0    ] = (O[ct][0] + Obuf[(r0    ) * 32 + c0]) * invA;
            ob[(size_t)c1 * HW + m0 + r0    ] = (O[ct][1] + Obuf[(r0    ) * 32 + c1]) * invA;
            ob[(size_t)c0 * HW + m0 + r0 + 8] = (O[ct][2] + Obuf[(r0 + 8) * 32 + c0]) * invB;
            ob[(size_t)c1 * HW + m0 + r0 + 8] = (O[ct][3] + Obuf[(r0 + 8) * 32 + c1]) * invB;
        }
    }
}

// ---------------- launch -----------------------------------------------------
extern "C" void kernel_launch(void* const* d_in, const int* in_sizes, int n_in,
                              void* d_out, int out_size) {
    const float* x      = (const float*)d_in[0];
    const float* Wq     = (const float*)d_in[1];
    const float* bq     = (const float*)d_in[2];
    const float* Wk     = (const float*)d_in[3];
    const float* bk     = (const float*)d_in[4];
    const float* Wv     = (const float*)d_in[5];
    const float* bv     = (const float*)d_in[6];
    const float* Wo     = (const float*)d_in[7];
    const float* bo     = (const float*)d_in[8];
    const float* dw_w   = (const float*)d_in[9];
    const float* dw_b   = (const float*)d_in[10];
    const float* ln_g   = (const float*)d_in[11];
    const float* ln_b   = (const float*)d_in[12];
    const float* pw_w   = (const float*)d_in[13];
    const float* rpe    = (const float*)d_in[14];
    float* y = (float*)d_out;

    float *q, *pos, *xs, *k, *v, *o;
    cudaGetSymbolAddress((void**)&q,   g_q);
    cudaGetSymbolAddress((void**)&pos, g_pos);
    cudaGetSymbolAddress((void**)&xs,  g_xs);
    cudaGetSymbolAddress((void**)&k,   g_k);
    cudaGetSymbolAddress((void**)&v,   g_v);
    cudaGetSymbolAddress((void**)&o,   g_o);

    static int smem_set = 0;
    if (!smem_set) {
        cudaFuncSetAttribute(attn4_kernel, cudaFuncAttributeMaxDynamicSharedMemorySize,
                             ATTN_SMEM_WORDS * 4);
        smem_set = 1;
    }

    dim3 ggrid(HW / BN, C_ / BM, B_);

    mma_gemm_kernel<<<ggrid, 128>>>(q, Wq, x, bq);

    dim3 ogrid(32, B_ * NGROUP);
    offset2_kernel<<<ogrid, 256>>>(q, dw_w, dw_b, ln_g, ln_b, pw_w, pos);

    sample_kernel<<<(B_ * NGROUP * GC * NS + 255) / 256, 256>>>(x, pos, xs);

    dim3 kvgrid(HW / BN, 12, B_);
    mma_gemm_kv_kernel<<<kvgrid, 128>>>(k, Wk, bk, v, Wv, bv, xs);

    dim3 agrid(HW / 64, B_ * NHEAD);
    attn4_kernel<<<agrid, 256, ATTN_SMEM_WORDS * 4>>>(q, k, v, pos, rpe, o);

    mma_gemm_kernel<<<ggrid, 128>>>(y, Wo, o, bo);
}